// round 7
// baseline (speedup 1.0000x reference)
#include <cuda_runtime.h>
#include <cuda_bf16.h>
#include <cuda_fp16.h>
#include <math.h>
#include <stdint.h>

#define NMAX 4096
#define DMAX 256
#define KPACK 768              // [hi|hi|lo] / [hi|lo|hi]
#define SCALE_F 10.0f
#define EPS_F 1e-5f
#define INF_F __int_as_float(0x7f800000)

__device__ float g_dist[(size_t)NMAX * NMAX];
__device__ float g_sq[NMAX];
__device__ unsigned char g_cam[NMAX];
__device__ float g_partial[NMAX];
__device__ int g_ctr = 0;
__device__ __nv_bfloat16 g_pa[(size_t)NMAX * KPACK];
__device__ __nv_bfloat16 g_pb[(size_t)NMAX * KPACK];

__device__ __forceinline__ uint32_t smem_to_u32(const void* p) {
    uint32_t a;
    asm("{ .reg .u64 t; cvta.to.shared.u64 t, %1; cvt.u32.u64 %0, t; }"
        : "=r"(a) : "l"(p));
    return a;
}

#define LDMATRIX_X4(R, addr) \
    asm volatile("ldmatrix.sync.aligned.m8n8.x4.shared.b16 {%0,%1,%2,%3}, [%4];" \
        : "=r"((R)[0]), "=r"((R)[1]), "=r"((R)[2]), "=r"((R)[3]) : "r"(addr))
#define MMA_BF16(D, A, B) \
    asm volatile("mma.sync.aligned.m16n8k16.row.col.f32.bf16.bf16.f32 " \
        "{%0,%1,%2,%3}, {%4,%5,%6,%7}, {%8,%9}, {%0,%1,%2,%3};" \
        : "+f"((D)[0]), "+f"((D)[1]), "+f"((D)[2]), "+f"((D)[3]) \
        : "r"((A)[0]), "r"((A)[1]), "r"((A)[2]), "r"((A)[3]), \
          "r"((B)[0]), "r"((B)[1]))
#define CP_ASYNC16(dst, src) \
    asm volatile("cp.async.cg.shared.global [%0], [%1], 16;" \
        :: "r"(dst), "l"(src))
#define CP_COMMIT() asm volatile("cp.async.commit_group;")
#define CP_WAIT(N)  asm volatile("cp.async.wait_group %0;" :: "n"(N))

// ===========================================================================
// Fused prep: warp-per-row split+pack+sq  |  camid normalize + counter reset
// ===========================================================================
__global__ void prep_fused_kernel(const float* __restrict__ f,
                                  const int* __restrict__ cam_raw,
                                  int n, int d, int rowBlocks) {
    int b = blockIdx.x;
    if (b < rowBlocks) {
        int row  = b * 8 + (threadIdx.x >> 5);
        int lane = threadIdx.x & 31;
        if (row >= n) return;
        const float4* src = (const float4*)(f + (size_t)row * d) + lane * 2;
        float4 x0 = src[0], x1 = src[1];    // 8 elems
        float xv[8] = {x0.x, x0.y, x0.z, x0.w, x1.x, x1.y, x1.z, x1.w};
        float s = 0.f;
        uint32_t hu[4], lu[4];
#pragma unroll
        for (int q = 0; q < 4; ++q) {
            float a = xv[2 * q], c = xv[2 * q + 1];
            s += a * a + c * c;
            __nv_bfloat16 h0 = __float2bfloat16_rn(a);
            __nv_bfloat16 h1 = __float2bfloat16_rn(c);
            __nv_bfloat16 l0 = __float2bfloat16_rn(a - __bfloat162float(h0));
            __nv_bfloat16 l1 = __float2bfloat16_rn(c - __bfloat162float(h1));
            __nv_bfloat162 hh(h0, h1), ll(l0, l1);
            hu[q] = *(uint32_t*)&hh;
            lu[q] = *(uint32_t*)&ll;
        }
#pragma unroll
        for (int off = 16; off; off >>= 1) s += __shfl_down_sync(0xffffffffu, s, off);
        if (lane == 0) g_sq[row] = s;

        uint4 hv = make_uint4(hu[0], hu[1], hu[2], hu[3]);
        uint4 lv = make_uint4(lu[0], lu[1], lu[2], lu[3]);
        uint4* pa4 = (uint4*)(g_pa + (size_t)row * KPACK);
        uint4* pb4 = (uint4*)(g_pb + (size_t)row * KPACK);
        pa4[lane] = hv; pa4[32 + lane] = hv; pa4[64 + lane] = lv;
        pb4[lane] = hv; pb4[32 + lane] = lv; pb4[64 + lane] = hv;
    } else {
        __shared__ int s_is64;
        if (threadIdx.x == 0) {
            g_ctr = 0;
            int is64 = 1;
            int checks = n < 128 ? n : 128;
            for (int k = 0; k < checks; ++k)
                if (cam_raw[2 * k + 1] != 0) { is64 = 0; break; }
            s_is64 = is64;
        }
        __syncthreads();
        int is64 = s_is64;
        for (int j = threadIdx.x; j < n; j += blockDim.x)
            g_cam[j] = (unsigned char)(is64 ? cam_raw[2 * j] : cam_raw[j]);
    }
}

// ===========================================================================
// Distance GEMM via mma.sync bf16, UPPER-TRIANGLE blocks only.
// (unchanged from round 5/6)
// ===========================================================================
#define NCHUNK (KPACK / 64)
#define BUF_BYTES 32768
#define TLDA 129
#define SMEM_GEMM_TOTAL (1024 + 3 * BUF_BYTES)

__global__ void __launch_bounds__(256) dist_gemm_mma(int n) {
    extern __shared__ char smem_raw[];
    uint32_t sraw = smem_to_u32(smem_raw);
    uint32_t sbase = (sraw + 1023) & ~1023u;
    int tid = threadIdx.x, lane = tid & 31, wid = tid >> 5;

    int NB = n >> 7;
    int t = blockIdx.x;
    int bi = (int)((2.0f * NB + 1.0f -
                    sqrtf((2.0f * NB + 1.0f) * (2.0f * NB + 1.0f) - 8.0f * t)) * 0.5f);
    if (bi < 0) bi = 0;
    if (bi > NB - 1) bi = NB - 1;
#define TRI_START(r) ((r) * NB - ((r) * ((r) - 1)) / 2)
    while (bi + 1 < NB && TRI_START(bi + 1) <= t) ++bi;
    while (bi > 0 && TRI_START(bi) > t) --bi;
    int bj = bi + (t - TRI_START(bi));
#undef TRI_START

    const char* pa = (const char*)(g_pa + (size_t)bi * 128 * KPACK);
    const char* pb = (const char*)(g_pb + (size_t)bj * 128 * KPACK);
    const int ROWB = KPACK * 2;

    int seg = tid & 7, r0 = tid >> 3;

#define LOAD_CHUNK(c, buf) do { \
    uint32_t abase_ = sbase + (buf) * BUF_BYTES; \
    uint32_t bbase_ = abase_ + 16384; \
    _Pragma("unroll") \
    for (int it = 0; it < 4; ++it) { \
        int row = r0 + it * 32; \
        uint32_t off = row * 128 + seg * 16; \
        off = off ^ ((off >> 3) & 0x70); \
        CP_ASYNC16(abase_ + off, pa + (size_t)row * ROWB + (c) * 128 + seg * 16); \
        CP_ASYNC16(bbase_ + off, pb + (size_t)row * ROWB + (c) * 128 + seg * 16); \
    } \
    CP_COMMIT(); \
} while (0)

    int wr = wid >> 2, wc = wid & 3;
    int wm = wr * 64, wn = wc * 32;

    float acc[4][4][4];
#pragma unroll
    for (int mt = 0; mt < 4; ++mt)
#pragma unroll
        for (int nt = 0; nt < 4; ++nt)
#pragma unroll
            for (int e = 0; e < 4; ++e) acc[mt][nt][e] = 0.f;

    LOAD_CHUNK(0, 0);
    LOAD_CHUNK(1, 1);
    for (int c = 0; c < NCHUNK; ++c) {
        if (c == NCHUNK - 1) CP_WAIT(0);
        else                 CP_WAIT(1);
        __syncthreads();
        if (c + 2 < NCHUNK) LOAD_CHUNK(c + 2, (c + 2) % 3);

        uint32_t abase = sbase + (c % 3) * BUF_BYTES;
        uint32_t bbase = abase + 16384;
#pragma unroll
        for (int kk = 0; kk < 4; ++kk) {
            uint32_t afr[4][4], bfr[4][2];
#pragma unroll
            for (int mt = 0; mt < 4; ++mt) {
                int row = wm + mt * 16 + (lane & 15);
                uint32_t off = row * 128 + kk * 32 + (lane >> 4) * 16;
                off = off ^ ((off >> 3) & 0x70);
                LDMATRIX_X4(afr[mt], abase + off);
            }
#pragma unroll
            for (int np = 0; np < 2; ++np) {
                int row = wn + np * 16 + ((lane >> 4) << 3) + (lane & 7);
                uint32_t off = row * 128 + kk * 32 + (((lane >> 3) & 1) << 4);
                off = off ^ ((off >> 3) & 0x70);
                uint32_t q[4];
                LDMATRIX_X4(q, bbase + off);
                bfr[np * 2 + 0][0] = q[0]; bfr[np * 2 + 0][1] = q[1];
                bfr[np * 2 + 1][0] = q[2]; bfr[np * 2 + 1][1] = q[3];
            }
#pragma unroll
            for (int mt = 0; mt < 4; ++mt)
#pragma unroll
                for (int nt = 0; nt < 4; ++nt)
                    MMA_BF16(acc[mt][nt], afr[mt], bfr[nt]);
        }
    }

    __shared__ float ssq[256];
    float* s_tile = (float*)(smem_raw + (sbase - sraw));
    if (tid < 128) ssq[tid] = g_sq[bi * 128 + tid];
    else           ssq[tid] = g_sq[bj * 128 + (tid - 128)];
    __syncthreads();

    int g4 = lane >> 2, t4 = lane & 3;
#pragma unroll
    for (int mt = 0; mt < 4; ++mt) {
#pragma unroll
        for (int half = 0; half < 2; ++half) {
            int r = wm + mt * 16 + g4 + half * 8;
            int gi = bi * 128 + r;
            float sqi = ssq[r];
#pragma unroll
            for (int nt = 0; nt < 4; ++nt) {
                int col = wn + nt * 8 + 2 * t4;
                int gj = bj * 128 + col;
                float2 o;
                float d0 = sqi + ssq[128 + col] + EPS_F
                           - 2.0f * acc[mt][nt][half * 2 + 0];
                float d1 = sqi + ssq[128 + col + 1] + EPS_F
                           - 2.0f * acc[mt][nt][half * 2 + 1];
                o.x = sqrtf(fmaxf(d0, 1e-12f));
                o.y = sqrtf(fmaxf(d1, 1e-12f));
                if (gi == gj)     o.x = sqrtf(EPS_F);
                if (gi == gj + 1) o.y = sqrtf(EPS_F);
                *(float2*)(g_dist + (size_t)gi * n + gj) = o;
                s_tile[r * TLDA + col]     = o.x;
                s_tile[r * TLDA + col + 1] = o.y;
            }
        }
    }

    if (bi != bj) {
        __syncthreads();
#pragma unroll
        for (int it = 0; it < 16; ++it) {
            int c = it * 8 + wid;
            float* orow = g_dist + (size_t)(bj * 128 + c) * n + bi * 128;
#pragma unroll
            for (int q = 0; q < 4; ++q) {
                int r = lane + q * 32;
                orow[r] = s_tile[r * TLDA + c];
            }
        }
    }
#undef LOAD_CHUNK
}

// ===========================================================================
// Row kernel: candidate-collection fast path + exact fallback.
// ===========================================================================
#define CAPI 1024
#define CAPE 2048
#define CUT  1.6f
#define DLI  3.2f
#define DLE  3.0f

#define INSERT7(t, val) do { \
    float _v = (val); \
    if (_v < t[6]) { \
        t[6] = _v; \
        _Pragma("unroll") \
        for (int _k = 6; _k > 0; --_k) { \
            float _a = t[_k-1], _b = t[_k]; \
            t[_k-1] = fminf(_a, _b); t[_k] = fmaxf(_a, _b); } \
    } } while (0)

__device__ __forceinline__ void warp_pop7(float t[7], int lane, float* out) {
#pragma unroll
    for (int r = 0; r < 7; ++r) {
        float bv = t[0]; int bl = lane;
#pragma unroll
        for (int off = 16; off; off >>= 1) {
            float ov = __shfl_down_sync(0xffffffffu, bv, off);
            int   ol = __shfl_down_sync(0xffffffffu, bl, off);
            if (ov < bv) { bv = ov; bl = ol; }
        }
        bv = __shfl_sync(0xffffffffu, bv, 0);
        bl = __shfl_sync(0xffffffffu, bl, 0);
        if (lane == bl) {
#pragma unroll
            for (int k = 0; k < 6; ++k) t[k] = t[k + 1];
            t[6] = INF_F;
        }
        if (lane == 0) out[r] = bv;
    }
}

// merge 8 per-warp sorted-7 lists; warp 0 -> set0 (K=4), warp 1 -> set1 (K=6)
__device__ __forceinline__ void merge_sel(int wid, int lane,
                                          float (*s_pop)[8][8],
                                          float (*s_res)[2]) {
    if (wid < 2) {
        float u[7];
#pragma unroll
        for (int k = 0; k < 7; ++k) u[k] = (lane < 8) ? s_pop[wid][lane][k] : INF_F;
        int K = (wid == 0) ? 4 : 6;
        float d0 = INF_F, dK = INF_F;
#pragma unroll
        for (int r = 0; r < 7; ++r) {
            float bv = u[0]; int bl = lane;
#pragma unroll
            for (int off = 16; off; off >>= 1) {
                float ov = __shfl_down_sync(0xffffffffu, bv, off);
                int   ol = __shfl_down_sync(0xffffffffu, bl, off);
                if (ov < bv) { bv = ov; bl = ol; }
            }
            bv = __shfl_sync(0xffffffffu, bv, 0);
            bl = __shfl_sync(0xffffffffu, bl, 0);
            if (lane == bl) {
#pragma unroll
                for (int k = 0; k < 6; ++k) u[k] = u[k + 1];
                u[6] = INF_F;
            }
            if (r == 0) d0 = bv;
            if (r == K) dK = bv;
        }
        if (lane == 0) { s_res[wid][0] = d0; s_res[wid][1] = dK; }
    }
}

__global__ void __launch_bounds__(256) row_kernel(int n, float* __restrict__ out) {
    __shared__ float sbI[CAPI];
    __shared__ float sbE[CAPE];
    __shared__ int   s_ti[8];
    __shared__ int   s_tot[8];
    __shared__ float s_mw[2][8];
    __shared__ float s_pop[2][8][8];
    __shared__ float s_res[2][2];
    __shared__ float s_sum[2][8];
    __shared__ int   s_lt[8];
    __shared__ int   s_cnt2;
    __shared__ float s_red[256];
    __shared__ int   s_last;

    int i = blockIdx.x, tid = threadIdx.x;
    int wid = tid >> 5, lane = tid & 31;
    const float* drow = g_dist + (size_t)i * n;
    int mycam = g_cam[i];

    float v[16];
    unsigned mk = 0, sfm = 0;
#pragma unroll
    for (int w = 0; w < 4; ++w) {
        int j = tid * 4 + w * 1024;
        float4 f = *(const float4*)(drow + j);
        v[w*4+0]=f.x; v[w*4+1]=f.y; v[w*4+2]=f.z; v[w*4+3]=f.w;
        uchar4 cc = ((const uchar4*)g_cam)[j >> 2];
        if (cc.x == mycam) mk |= 1u << (w*4+0);
        if (cc.y == mycam) mk |= 1u << (w*4+1);
        if (cc.z == mycam) mk |= 1u << (w*4+2);
        if (cc.w == mycam) mk |= 1u << (w*4+3);
        if (j     == i) sfm |= 1u << (w*4+0);
        if (j + 1 == i) sfm |= 1u << (w*4+1);
        if (j + 2 == i) sfm |= 1u << (w*4+2);
        if (j + 3 == i) sfm |= 1u << (w*4+3);
    }

    // per-thread mins (self excluded) + set sizes (packed)
    float mnI = INF_F, mnE = INF_F;
    int cTot = 0;
#pragma unroll
    for (int k = 0; k < 16; ++k) {
        bool isI = (mk >> k) & 1, isS = (sfm >> k) & 1;
        if (!isS) {
            if (isI) { mnI = fminf(mnI, v[k]); cTot += 1; }
            else     { mnE = fminf(mnE, v[k]); cTot += 1 << 16; }
        }
    }
#pragma unroll
    for (int off = 16; off; off >>= 1) {
        mnI = fminf(mnI, __shfl_xor_sync(0xffffffffu, mnI, off));
        mnE = fminf(mnE, __shfl_xor_sync(0xffffffffu, mnE, off));
        cTot += __shfl_xor_sync(0xffffffffu, cTot, off);
    }
    if (lane == 0) { s_mw[0][wid] = mnI; s_mw[1][wid] = mnE; s_tot[wid] = cTot; }
    __syncthreads();
    float mI = INF_F, mE = INF_F; int tot = 0;
#pragma unroll
    for (int w = 0; w < 8; ++w) {
        mI = fminf(mI, s_mw[0][w]); mE = fminf(mE, s_mw[1][w]); tot += s_tot[w];
    }
    int totI = (tot & 0xffff) + 1;       // + self
    int totE = tot >> 16;
    float tI = mI + DLI, tE = mE + DLE;

    // candidate picks + deterministic block scan (packed counts)
    unsigned pI = 0, pE = 0;
#pragma unroll
    for (int k = 0; k < 16; ++k) {
        bool isI = (mk >> k) & 1, isS = (sfm >> k) & 1;
        if (!isS) {
            if (isI) { if (v[k] < tI) pI |= 1u << k; }
            else     { if (v[k] < tE) pE |= 1u << k; }
        }
    }
    int packed = __popc(pI) | (__popc(pE) << 16);
    int incl = packed;
#pragma unroll
    for (int off = 1; off < 32; off <<= 1) {
        int tt = __shfl_up_sync(0xffffffffu, incl, off);
        if (lane >= off) incl += tt;
    }
    if (lane == 31) s_ti[wid] = incl;
    __syncthreads();
    if (tid < 8) {
        int t0 = s_ti[tid], inc2 = t0;
#pragma unroll
        for (int off = 1; off < 8; off <<= 1) {
            int u = __shfl_up_sync(0xffu, inc2, off);
            if (tid >= off) inc2 += u;
        }
        s_ti[tid] = inc2 - t0;
        if (tid == 7) s_cnt2 = inc2;
    }
    __syncthreads();
    int base = (incl - packed) + s_ti[wid];
    int cntI = s_cnt2 & 0xffff, cntE = s_cnt2 >> 16;
    bool fb = (cntI + 1 > CAPI) || (cntE > CAPE);
    int nI = cntI + 1, nE = cntE;

    if (!fb) {
        int oI = base & 0xffff, oE = base >> 16;
#pragma unroll
        for (int k = 0; k < 16; ++k) {
            if ((pI >> k) & 1)      sbI[oI++] = v[k];
            else if ((pE >> k) & 1) sbE[oE++] = v[k];
        }
        if (tid == 0) sbI[cntI] = sqrtf(EPS_F);      // self (combined rank 0)
        __syncthreads();

        float t7I[7], t7E[7];
#pragma unroll
        for (int k = 0; k < 7; ++k) { t7I[k] = INF_F; t7E[k] = INF_F; }
        for (int idx = tid; idx < nI; idx += 256) INSERT7(t7I, sbI[idx]);
        for (int idx = tid; idx < nE; idx += 256) INSERT7(t7E, sbE[idx]);
        warp_pop7(t7I, lane, &s_pop[0][wid][0]);
        warp_pop7(t7E, lane, &s_pop[1][wid][0]);
        __syncthreads();
        merge_sel(wid, lane, s_pop, s_res);
        __syncthreads();
    }
    float d0i = s_res[0][0], dKi = s_res[0][1];
    float d0e = s_res[1][0], dKe = s_res[1][1];

    bool needI = totI > 4, needE = totE > 6;
    bool fastI = !needI || (!fb && (dKi + CUT <= tI));
    bool fastE = !needE || (!fb && (dKe + CUT <= tE));

    if (fastI && fastE) {
        float sI = 0.f, sE = 0.f; int lt = 0;
        if (needI)
            for (int idx = tid; idx < nI; idx += 256) {
                float x = sbI[idx];
                if (x >= dKi) sI += __expf(SCALE_F * (dKi - x)); else lt += 1;
            }
        if (needE)
            for (int idx = tid; idx < nE; idx += 256) {
                float x = sbE[idx];
                if (x >= dKe) sE += __expf(SCALE_F * (dKe - x)); else lt += 1 << 16;
            }
#pragma unroll
        for (int off = 16; off; off >>= 1) {
            sI += __shfl_xor_sync(0xffffffffu, sI, off);
            sE += __shfl_xor_sync(0xffffffffu, sE, off);
            lt += __shfl_xor_sync(0xffffffffu, lt, off);
        }
        if (lane == 0) { s_sum[0][wid] = sI; s_sum[1][wid] = sE; s_lt[wid] = lt; }
    } else {
        // exact fallback: full-set selection + full sum (both sets)
        __syncthreads();
        float ti7[7], te7[7];
#pragma unroll
        for (int k = 0; k < 7; ++k) { ti7[k] = INF_F; te7[k] = INF_F; }
#pragma unroll
        for (int k = 0; k < 16; ++k) {
            if ((mk >> k) & 1) INSERT7(ti7, v[k]);   // self included (== sqrt(eps))
            else               INSERT7(te7, v[k]);
        }
        warp_pop7(ti7, lane, &s_pop[0][wid][0]);
        warp_pop7(te7, lane, &s_pop[1][wid][0]);
        __syncthreads();
        merge_sel(wid, lane, s_pop, s_res);
        __syncthreads();
        d0i = s_res[0][0]; dKi = s_res[0][1];
        d0e = s_res[1][0]; dKe = s_res[1][1];
        float sI = 0.f, sE = 0.f; int lt = 0;
#pragma unroll
        for (int k = 0; k < 16; ++k) {
            float x = v[k];
            if ((mk >> k) & 1) {
                if (x >= dKi) sI += __expf(SCALE_F * (dKi - x)); else lt += 1;
            } else {
                if (x >= dKe) sE += __expf(SCALE_F * (dKe - x)); else lt += 1 << 16;
            }
        }
#pragma unroll
        for (int off = 16; off; off >>= 1) {
            sI += __shfl_xor_sync(0xffffffffu, sI, off);
            sE += __shfl_xor_sync(0xffffffffu, sE, off);
            lt += __shfl_xor_sync(0xffffffffu, lt, off);
        }
        if (lane == 0) { s_sum[0][wid] = sI; s_sum[1][wid] = sE; s_lt[wid] = lt; }
    }
    __syncthreads();

    if (tid == 0) {
        float SI = 0.f, SE = 0.f; int LT = 0;
#pragma unroll
        for (int w = 0; w < 8; ++w) { SI += s_sum[0][w]; SE += s_sum[1][w]; LT += s_lt[w]; }
        int ltI = LT & 0xffff, ltE = LT >> 16;
        float termI = 0.f, termE = 0.f;
        if (needI) {
            SI -= (float)(4 - ltI);                 // tie correction (usually 0)
            termI = fmaxf(SCALE_F * (d0i - dKi) + logf(SI) + 40.0f, 0.f);
        }
        if (needE) {
            SE -= (float)(6 - ltE);
            termE = fmaxf(SCALE_F * (d0e - dKe) + logf(SE) + 6.0f, 0.f);
        }
        g_partial[i] = termI + 0.5f * termE;
        __threadfence();
        int old = atomicAdd(&g_ctr, 1);
        s_last = (old == n - 1);
    }
    __syncthreads();

    if (s_last) {
        float s = 0.f;
        for (int j = tid; j < n; j += 256) s += g_partial[j];
        s_red[tid] = s;
        __syncthreads();
        for (int st = 128; st; st >>= 1) {
            if (tid < st) s_red[tid] += s_red[tid + st];
            __syncthreads();
        }
        if (tid == 0) { out[0] = s_red[0] / (float)n; g_ctr = 0; }
    }
}

// ===========================================================================
extern "C" void kernel_launch(void* const* d_in, const int* in_sizes, int n_in,
                              void* d_out, int out_size) {
    const float* feat = (const float*)d_in[0];
    const int*   cam  = (const int*)d_in[1];
    int n = in_sizes[1];
    int d = in_sizes[0] / n;
    int NB = n / 128;

    static int smem_set = 0;
    if (!smem_set) {
        cudaFuncSetAttribute(dist_gemm_mma,
                             cudaFuncAttributeMaxDynamicSharedMemorySize,
                             SMEM_GEMM_TOTAL);
        smem_set = 1;
    }

    int rowBlocks = (n + 7) / 8;
    prep_fused_kernel<<<rowBlocks + 1, 256>>>(feat, cam, n, d, rowBlocks);
    dist_gemm_mma<<<NB * (NB + 1) / 2, 256, SMEM_GEMM_TOTAL>>>(n);
    row_kernel<<<n, 256>>>(n, (float*)d_out);
}

// round 8
// speedup vs baseline: 1.1874x; 1.1874x over previous
#include <cuda_runtime.h>
#include <cuda_bf16.h>
#include <cuda_fp16.h>
#include <math.h>
#include <stdint.h>

#define NMAX 4096
#define DMAX 256
#define KPACK 768              // A pack: [hi|hi|lo]; B = chunk-permutation of A
#define SCALE_F 10.0f
#define EPS_F 1e-5f
#define INF_F __int_as_float(0x7f800000)
#define L2E10 14.4269504089f   // 10 * log2(e)

__device__ float g_dist[(size_t)NMAX * NMAX];
__device__ float g_sq[NMAX];
__device__ unsigned char g_cam[NMAX];
__device__ float g_partial[NMAX];
__device__ int g_ctr = 0;
__device__ __nv_bfloat16 g_pa[(size_t)NMAX * KPACK];

__device__ __forceinline__ uint32_t smem_to_u32(const void* p) {
    uint32_t a;
    asm("{ .reg .u64 t; cvta.to.shared.u64 t, %1; cvt.u32.u64 %0, t; }"
        : "=r"(a) : "l"(p));
    return a;
}

#define LDMATRIX_X4(R, addr) \
    asm volatile("ldmatrix.sync.aligned.m8n8.x4.shared.b16 {%0,%1,%2,%3}, [%4];" \
        : "=r"((R)[0]), "=r"((R)[1]), "=r"((R)[2]), "=r"((R)[3]) : "r"(addr))
#define MMA_BF16(D, A, B) \
    asm volatile("mma.sync.aligned.m16n8k16.row.col.f32.bf16.bf16.f32 " \
        "{%0,%1,%2,%3}, {%4,%5,%6,%7}, {%8,%9}, {%0,%1,%2,%3};" \
        : "+f"((D)[0]), "+f"((D)[1]), "+f"((D)[2]), "+f"((D)[3]) \
        : "r"((A)[0]), "r"((A)[1]), "r"((A)[2]), "r"((A)[3]), \
          "r"((B)[0]), "r"((B)[1]))
#define CP_ASYNC16(dst, src) \
    asm volatile("cp.async.cg.shared.global [%0], [%1], 16;" \
        :: "r"(dst), "l"(src))
#define CP_COMMIT() asm volatile("cp.async.commit_group;")
#define CP_WAIT(N)  asm volatile("cp.async.wait_group %0;" :: "n"(N))

// ===========================================================================
// Fused prep: warp-per-row split+pack+sq  |  camid normalize + counter reset
// ===========================================================================
__global__ void prep_fused_kernel(const float* __restrict__ f,
                                  const int* __restrict__ cam_raw,
                                  int n, int d, int rowBlocks) {
    int b = blockIdx.x;
    if (b < rowBlocks) {
        int row  = b * 8 + (threadIdx.x >> 5);
        int lane = threadIdx.x & 31;
        if (row >= n) return;
        const float4* src = (const float4*)(f + (size_t)row * d) + lane * 2;
        float4 x0 = src[0], x1 = src[1];    // 8 elems
        float xv[8] = {x0.x, x0.y, x0.z, x0.w, x1.x, x1.y, x1.z, x1.w};
        float s = 0.f;
        uint32_t hu[4], lu[4];
#pragma unroll
        for (int q = 0; q < 4; ++q) {
            float a = xv[2 * q], c = xv[2 * q + 1];
            s += a * a + c * c;
            __nv_bfloat16 h0 = __float2bfloat16_rn(a);
            __nv_bfloat16 h1 = __float2bfloat16_rn(c);
            __nv_bfloat16 l0 = __float2bfloat16_rn(a - __bfloat162float(h0));
            __nv_bfloat16 l1 = __float2bfloat16_rn(c - __bfloat162float(h1));
            __nv_bfloat162 hh(h0, h1), ll(l0, l1);
            hu[q] = *(uint32_t*)&hh;
            lu[q] = *(uint32_t*)&ll;
        }
#pragma unroll
        for (int off = 16; off; off >>= 1) s += __shfl_down_sync(0xffffffffu, s, off);
        if (lane == 0) g_sq[row] = s;

        uint4 hv = make_uint4(hu[0], hu[1], hu[2], hu[3]);
        uint4 lv = make_uint4(lu[0], lu[1], lu[2], lu[3]);
        uint4* pa4 = (uint4*)(g_pa + (size_t)row * KPACK);
        pa4[lane] = hv; pa4[32 + lane] = hv; pa4[64 + lane] = lv;
    } else {
        __shared__ int s_is64;
        if (threadIdx.x == 0) {
            g_ctr = 0;
            int is64 = 1;
            int checks = n < 128 ? n : 128;
            for (int k = 0; k < checks; ++k)
                if (cam_raw[2 * k + 1] != 0) { is64 = 0; break; }
            s_is64 = is64;
        }
        __syncthreads();
        int is64 = s_is64;
        for (int j = threadIdx.x; j < n; j += blockDim.x)
            g_cam[j] = (unsigned char)(is64 ? cam_raw[2 * j] : cam_raw[j]);
    }
}

// ===========================================================================
// Distance GEMM via mma.sync bf16, UPPER-TRIANGLE blocks only.
// B tile = g_pa with chunk remap: A chunks [hi0-3|hi4-7|lo8-11],
// B needs [hi|lo|hi] -> chunk map c<4: c ; 4<=c<8: c+4 ; c>=8: c-4.
// ===========================================================================
#define NCHUNK (KPACK / 64)
#define BUF_BYTES 32768
#define TLDA 129
#define SMEM_GEMM_TOTAL (1024 + 3 * BUF_BYTES)

__global__ void __launch_bounds__(256, 2) dist_gemm_mma(int n) {
    extern __shared__ char smem_raw[];
    uint32_t sraw = smem_to_u32(smem_raw);
    uint32_t sbase = (sraw + 1023) & ~1023u;
    int tid = threadIdx.x, lane = tid & 31, wid = tid >> 5;

    int NB = n >> 7;
    int t = blockIdx.x;
    int bi = (int)((2.0f * NB + 1.0f -
                    sqrtf((2.0f * NB + 1.0f) * (2.0f * NB + 1.0f) - 8.0f * t)) * 0.5f);
    if (bi < 0) bi = 0;
    if (bi > NB - 1) bi = NB - 1;
#define TRI_START(r) ((r) * NB - ((r) * ((r) - 1)) / 2)
    while (bi + 1 < NB && TRI_START(bi + 1) <= t) ++bi;
    while (bi > 0 && TRI_START(bi) > t) --bi;
    int bj = bi + (t - TRI_START(bi));
#undef TRI_START

    const char* pa = (const char*)(g_pa + (size_t)bi * 128 * KPACK);
    const char* pb = (const char*)(g_pa + (size_t)bj * 128 * KPACK);
    const int ROWB = KPACK * 2;

    int seg = tid & 7, r0 = tid >> 3;

#define LOAD_CHUNK(c, buf) do { \
    int cb_ = ((c) < 4) ? (c) : (((c) < 8) ? (c) + 4 : (c) - 4); \
    uint32_t abase_ = sbase + (buf) * BUF_BYTES; \
    uint32_t bbase_ = abase_ + 16384; \
    _Pragma("unroll") \
    for (int it = 0; it < 4; ++it) { \
        int row = r0 + it * 32; \
        uint32_t off = row * 128 + seg * 16; \
        off = off ^ ((off >> 3) & 0x70); \
        CP_ASYNC16(abase_ + off, pa + (size_t)row * ROWB + (c) * 128 + seg * 16); \
        CP_ASYNC16(bbase_ + off, pb + (size_t)row * ROWB + cb_ * 128 + seg * 16); \
    } \
    CP_COMMIT(); \
} while (0)

    int wr = wid >> 2, wc = wid & 3;
    int wm = wr * 64, wn = wc * 32;

    float acc[4][4][4];
#pragma unroll
    for (int mt = 0; mt < 4; ++mt)
#pragma unroll
        for (int nt = 0; nt < 4; ++nt)
#pragma unroll
            for (int e = 0; e < 4; ++e) acc[mt][nt][e] = 0.f;

    LOAD_CHUNK(0, 0);
    LOAD_CHUNK(1, 1);
    for (int c = 0; c < NCHUNK; ++c) {
        if (c == NCHUNK - 1) CP_WAIT(0);
        else                 CP_WAIT(1);
        __syncthreads();
        if (c + 2 < NCHUNK) LOAD_CHUNK(c + 2, (c + 2) % 3);

        uint32_t abase = sbase + (c % 3) * BUF_BYTES;
        uint32_t bbase = abase + 16384;
#pragma unroll
        for (int kk = 0; kk < 4; ++kk) {
            uint32_t afr[4][4], bfr[4][2];
#pragma unroll
            for (int mt = 0; mt < 4; ++mt) {
                int row = wm + mt * 16 + (lane & 15);
                uint32_t off = row * 128 + kk * 32 + (lane >> 4) * 16;
                off = off ^ ((off >> 3) & 0x70);
                LDMATRIX_X4(afr[mt], abase + off);
            }
#pragma unroll
            for (int np = 0; np < 2; ++np) {
                int row = wn + np * 16 + ((lane >> 4) << 3) + (lane & 7);
                uint32_t off = row * 128 + kk * 32 + (((lane >> 3) & 1) << 4);
                off = off ^ ((off >> 3) & 0x70);
                uint32_t q[4];
                LDMATRIX_X4(q, bbase + off);
                bfr[np * 2 + 0][0] = q[0]; bfr[np * 2 + 0][1] = q[1];
                bfr[np * 2 + 1][0] = q[2]; bfr[np * 2 + 1][1] = q[3];
            }
#pragma unroll
            for (int mt = 0; mt < 4; ++mt)
#pragma unroll
                for (int nt = 0; nt < 4; ++nt)
                    MMA_BF16(acc[mt][nt], afr[mt], bfr[nt]);
        }
    }

    __shared__ float ssq[256];
    float* s_tile = (float*)(smem_raw + (sbase - sraw));
    if (tid < 128) ssq[tid] = g_sq[bi * 128 + tid];
    else           ssq[tid] = g_sq[bj * 128 + (tid - 128)];
    __syncthreads();

    int g4 = lane >> 2, t4 = lane & 3;
#pragma unroll
    for (int mt = 0; mt < 4; ++mt) {
#pragma unroll
        for (int half = 0; half < 2; ++half) {
            int r = wm + mt * 16 + g4 + half * 8;
            int gi = bi * 128 + r;
            float sqi = ssq[r];
#pragma unroll
            for (int nt = 0; nt < 4; ++nt) {
                int col = wn + nt * 8 + 2 * t4;
                int gj = bj * 128 + col;
                float2 o;
                float d0 = sqi + ssq[128 + col] + EPS_F
                           - 2.0f * acc[mt][nt][half * 2 + 0];
                float d1 = sqi + ssq[128 + col + 1] + EPS_F
                           - 2.0f * acc[mt][nt][half * 2 + 1];
                o.x = sqrtf(fmaxf(d0, 1e-12f));
                o.y = sqrtf(fmaxf(d1, 1e-12f));
                if (gi == gj)     o.x = sqrtf(EPS_F);
                if (gi == gj + 1) o.y = sqrtf(EPS_F);
                *(float2*)(g_dist + (size_t)gi * n + gj) = o;
                s_tile[r * TLDA + col]     = o.x;
                s_tile[r * TLDA + col + 1] = o.y;
            }
        }
    }

    if (bi != bj) {
        __syncthreads();
#pragma unroll
        for (int it = 0; it < 16; ++it) {
            int c = it * 8 + wid;
            float* orow = g_dist + (size_t)(bj * 128 + c) * n + bi * 128;
#pragma unroll
            for (int q = 0; q < 4; ++q) {
                int r = lane + q * 32;
                orow[r] = s_tile[r * TLDA + c];
            }
        }
    }
#undef LOAD_CHUNK
}

// ===========================================================================
// Per-row selection + logsumexp (R6 version: registers + warp pop-merge +
// f16x2 exp). Last CTA does the deterministic final reduction.
// ===========================================================================
#define INSERT7(t, val) do { \
    float _v = (val); \
    if (_v < t[6]) { \
        t[6] = _v; \
        _Pragma("unroll") \
        for (int _k = 6; _k > 0; --_k) { \
            float _a = t[_k-1], _b = t[_k]; \
            t[_k-1] = fminf(_a, _b); t[_k] = fmaxf(_a, _b); } \
    } } while (0)

__device__ __forceinline__ void warp_pop7(float t[7], int lane, float* out) {
#pragma unroll
    for (int r = 0; r < 7; ++r) {
        float bv = t[0]; int bl = lane;
#pragma unroll
        for (int off = 16; off; off >>= 1) {
            float ov = __shfl_down_sync(0xffffffffu, bv, off);
            int   ol = __shfl_down_sync(0xffffffffu, bl, off);
            if (ov < bv) { bv = ov; bl = ol; }
        }
        bv = __shfl_sync(0xffffffffu, bv, 0);
        bl = __shfl_sync(0xffffffffu, bl, 0);
        if (lane == bl) {
#pragma unroll
            for (int k = 0; k < 6; ++k) t[k] = t[k + 1];
            t[6] = INF_F;
        }
        if (lane == 0) out[r] = bv;
    }
}

__global__ void __launch_bounds__(256) row_kernel(int n, float* __restrict__ out) {
    __shared__ float s_pop[2][8][8];
    __shared__ float s_res[2][2];
    __shared__ float s_sum[2][8];
    __shared__ float s_red[256];
    __shared__ int   s_last;

    int i = blockIdx.x, tid = threadIdx.x;
    int wid = tid >> 5, lane = tid & 31;
    const float* drow = g_dist + (size_t)i * n;
    int mycam = g_cam[i];

    float v[16];
    bool  m[16];
#pragma unroll
    for (int w = 0; w < 4; ++w) {
        int j = tid * 4 + w * 1024;
        float4 f = *(const float4*)(drow + j);
        v[w * 4 + 0] = f.x; v[w * 4 + 1] = f.y;
        v[w * 4 + 2] = f.z; v[w * 4 + 3] = f.w;
        uchar4 cc = ((const uchar4*)g_cam)[j >> 2];
        m[w * 4 + 0] = (cc.x == mycam); m[w * 4 + 1] = (cc.y == mycam);
        m[w * 4 + 2] = (cc.z == mycam); m[w * 4 + 3] = (cc.w == mycam);
    }

    float ti[7], te[7];
#pragma unroll
    for (int k = 0; k < 7; ++k) { ti[k] = INF_F; te[k] = INF_F; }
#pragma unroll
    for (int k = 0; k < 16; ++k) {
        if (m[k]) INSERT7(ti, v[k]);
        else      INSERT7(te, v[k]);
    }

    warp_pop7(ti, lane, &s_pop[0][wid][0]);
    warp_pop7(te, lane, &s_pop[1][wid][0]);
    __syncthreads();

    if (wid < 2) {   // warp 0: intra (K=4), warp 1: inter (K=6)
        float u[7];
#pragma unroll
        for (int k = 0; k < 7; ++k) u[k] = (lane < 8) ? s_pop[wid][lane][k] : INF_F;
        int K = (wid == 0) ? 4 : 6;
        float d0 = INF_F, dK = INF_F;
#pragma unroll
        for (int r = 0; r < 7; ++r) {
            float bv = u[0]; int bl = lane;
#pragma unroll
            for (int off = 16; off; off >>= 1) {
                float ov = __shfl_down_sync(0xffffffffu, bv, off);
                int   ol = __shfl_down_sync(0xffffffffu, bl, off);
                if (ov < bv) { bv = ov; bl = ol; }
            }
            bv = __shfl_sync(0xffffffffu, bv, 0);
            bl = __shfl_sync(0xffffffffu, bl, 0);
            if (lane == bl) {
#pragma unroll
                for (int k = 0; k < 6; ++k) u[k] = u[k + 1];
                u[6] = INF_F;
            }
            if (r == 0) d0 = bv;
            if (r == K) dK = bv;
        }
        if (lane == 0) { s_res[wid][0] = d0; s_res[wid][1] = dK; }
    }
    __syncthreads();

    float dKi = s_res[0][1], dKe = s_res[1][1];
    float CI = L2E10 * dKi, CE = L2E10 * dKe;
    float si = 0.f, se = 0.f;
#pragma unroll
    for (int k = 0; k < 16; k += 2) {
        float sel0 = m[k]     ? dKi : dKe;
        float sel1 = m[k + 1] ? dKi : dKe;
        float a0 = fmaf(-L2E10, v[k],     m[k]     ? CI : CE);
        float a1 = fmaf(-L2E10, v[k + 1], m[k + 1] ? CI : CE);
        a0 = (v[k]     >= sel0) ? fminf(a0, 0.f) : -100.f;
        a1 = (v[k + 1] >= sel1) ? fminf(a1, 0.f) : -100.f;
        __half2 h = h2exp2(__floats2half2_rn(a0, a1));
        float2 r2 = __half22float2(h);
        si += m[k]     ? r2.x : 0.f;  se += m[k]     ? 0.f : r2.x;
        si += m[k + 1] ? r2.y : 0.f;  se += m[k + 1] ? 0.f : r2.y;
    }
#pragma unroll
    for (int off = 16; off; off >>= 1) {
        si += __shfl_down_sync(0xffffffffu, si, off);
        se += __shfl_down_sync(0xffffffffu, se, off);
    }
    if (lane == 0) { s_sum[0][wid] = si; s_sum[1][wid] = se; }
    __syncthreads();

    if (tid == 0) {
        float Si = 0.f, Se = 0.f;
#pragma unroll
        for (int w = 0; w < 8; ++w) { Si += s_sum[0][w]; Se += s_sum[1][w]; }
        float d0i = s_res[0][0], d0e = s_res[1][0];
        float term_i = 0.f, term_e = 0.f;
        if (isfinite(dKi))
            term_i = fmaxf(SCALE_F * (d0i - dKi) + logf(Si) + 40.0f, 0.f);
        if (isfinite(dKe))
            term_e = fmaxf(SCALE_F * (d0e - dKe) + logf(Se) + 6.0f, 0.f);
        g_partial[i] = term_i + 0.5f * term_e;
        __threadfence();
        int old = atomicAdd(&g_ctr, 1);
        s_last = (old == n - 1);
    }
    __syncthreads();

    if (s_last) {
        float s = 0.f;
        for (int j = tid; j < n; j += 256) s += g_partial[j];
        s_red[tid] = s;
        __syncthreads();
        for (int st = 128; st; st >>= 1) {
            if (tid < st) s_red[tid] += s_red[tid + st];
            __syncthreads();
        }
        if (tid == 0) { out[0] = s_red[0] / (float)n; g_ctr = 0; }
    }
}

// ===========================================================================
extern "C" void kernel_launch(void* const* d_in, const int* in_sizes, int n_in,
                              void* d_out, int out_size) {
    const float* feat = (const float*)d_in[0];
    const int*   cam  = (const int*)d_in[1];
    int n = in_sizes[1];
    int d = in_sizes[0] / n;
    int NB = n / 128;

    static int smem_set = 0;
    if (!smem_set) {
        cudaFuncSetAttribute(dist_gemm_mma,
                             cudaFuncAttributeMaxDynamicSharedMemorySize,
                             SMEM_GEMM_TOTAL);
        smem_set = 1;
    }

    int rowBlocks = (n + 7) / 8;
    prep_fused_kernel<<<rowBlocks + 1, 256>>>(feat, cam, n, d, rowBlocks);
    dist_gemm_mma<<<NB * (NB + 1) / 2, 256, SMEM_GEMM_TOTAL>>>(n);
    row_kernel<<<n, 256>>>(n, (float*)d_out);
}

// round 9
// speedup vs baseline: 1.2301x; 1.0359x over previous
#include <cuda_runtime.h>
#include <cuda_bf16.h>
#include <math.h>
#include <stdint.h>

#define NMAX 4096
#define DMAX 256
#define KPACK 768              // A pack: [hi|hi|lo]; B = chunk-permutation of A
#define SCALE_F 10.0f
#define EPS_F 1e-5f
#define INF_F __int_as_float(0x7f800000)
#define DELTA 1.0f

__device__ float g_dist[(size_t)NMAX * NMAX];
__device__ float g_sq[NMAX];
__device__ unsigned char g_cam[NMAX];
__device__ float g_partial[NMAX];
__device__ int g_ctr = 0;
__device__ __nv_bfloat16 g_pa[(size_t)NMAX * KPACK];

__device__ __forceinline__ uint32_t smem_to_u32(const void* p) {
    uint32_t a;
    asm("{ .reg .u64 t; cvta.to.shared.u64 t, %1; cvt.u32.u64 %0, t; }"
        : "=r"(a) : "l"(p));
    return a;
}

#define LDMATRIX_X4(R, addr) \
    asm volatile("ldmatrix.sync.aligned.m8n8.x4.shared.b16 {%0,%1,%2,%3}, [%4];" \
        : "=r"((R)[0]), "=r"((R)[1]), "=r"((R)[2]), "=r"((R)[3]) : "r"(addr))
#define MMA_BF16(D, A, B) \
    asm volatile("mma.sync.aligned.m16n8k16.row.col.f32.bf16.bf16.f32 " \
        "{%0,%1,%2,%3}, {%4,%5,%6,%7}, {%8,%9}, {%0,%1,%2,%3};" \
        : "+f"((D)[0]), "+f"((D)[1]), "+f"((D)[2]), "+f"((D)[3]) \
        : "r"((A)[0]), "r"((A)[1]), "r"((A)[2]), "r"((A)[3]), \
          "r"((B)[0]), "r"((B)[1]))
#define CP_ASYNC16(dst, src) \
    asm volatile("cp.async.cg.shared.global [%0], [%1], 16;" \
        :: "r"(dst), "l"(src))
#define CP_COMMIT() asm volatile("cp.async.commit_group;")
#define CP_WAIT(N)  asm volatile("cp.async.wait_group %0;" :: "n"(N))

// ===========================================================================
// Fused prep: warp-per-row split+pack+sq  |  camid normalize + counter reset
// ===========================================================================
__global__ void prep_fused_kernel(const float* __restrict__ f,
                                  const int* __restrict__ cam_raw,
                                  int n, int d, int rowBlocks) {
    int b = blockIdx.x;
    if (b < rowBlocks) {
        int row  = b * 8 + (threadIdx.x >> 5);
        int lane = threadIdx.x & 31;
        if (row >= n) return;
        const float4* src = (const float4*)(f + (size_t)row * d) + lane * 2;
        float4 x0 = src[0], x1 = src[1];
        float xv[8] = {x0.x, x0.y, x0.z, x0.w, x1.x, x1.y, x1.z, x1.w};
        float s = 0.f;
        uint32_t hu[4], lu[4];
#pragma unroll
        for (int q = 0; q < 4; ++q) {
            float a = xv[2 * q], c = xv[2 * q + 1];
            s += a * a + c * c;
            __nv_bfloat16 h0 = __float2bfloat16_rn(a);
            __nv_bfloat16 h1 = __float2bfloat16_rn(c);
            __nv_bfloat16 l0 = __float2bfloat16_rn(a - __bfloat162float(h0));
            __nv_bfloat16 l1 = __float2bfloat16_rn(c - __bfloat162float(h1));
            __nv_bfloat162 hh(h0, h1), ll(l0, l1);
            hu[q] = *(uint32_t*)&hh;
            lu[q] = *(uint32_t*)&ll;
        }
#pragma unroll
        for (int off = 16; off; off >>= 1) s += __shfl_down_sync(0xffffffffu, s, off);
        if (lane == 0) g_sq[row] = s;

        uint4 hv = make_uint4(hu[0], hu[1], hu[2], hu[3]);
        uint4 lv = make_uint4(lu[0], lu[1], lu[2], lu[3]);
        uint4* pa4 = (uint4*)(g_pa + (size_t)row * KPACK);
        pa4[lane] = hv; pa4[32 + lane] = hv; pa4[64 + lane] = lv;
    } else {
        __shared__ int s_is64;
        if (threadIdx.x == 0) {
            g_ctr = 0;
            int is64 = 1;
            int checks = n < 128 ? n : 128;
            for (int k = 0; k < checks; ++k)
                if (cam_raw[2 * k + 1] != 0) { is64 = 0; break; }
            s_is64 = is64;
        }
        __syncthreads();
        int is64 = s_is64;
        for (int j = threadIdx.x; j < n; j += blockDim.x)
            g_cam[j] = (unsigned char)(is64 ? cam_raw[2 * j] : cam_raw[j]);
    }
}

// ===========================================================================
// Distance GEMM via mma.sync bf16, UPPER-TRIANGLE blocks only. (unchanged)
// ===========================================================================
#define NCHUNK (KPACK / 64)
#define BUF_BYTES 32768
#define TLDA 129
#define SMEM_GEMM_TOTAL (1024 + 3 * BUF_BYTES)

__global__ void __launch_bounds__(256, 2) dist_gemm_mma(int n) {
    extern __shared__ char smem_raw[];
    uint32_t sraw = smem_to_u32(smem_raw);
    uint32_t sbase = (sraw + 1023) & ~1023u;
    int tid = threadIdx.x, lane = tid & 31, wid = tid >> 5;

    int NB = n >> 7;
    int t = blockIdx.x;
    int bi = (int)((2.0f * NB + 1.0f -
                    sqrtf((2.0f * NB + 1.0f) * (2.0f * NB + 1.0f) - 8.0f * t)) * 0.5f);
    if (bi < 0) bi = 0;
    if (bi > NB - 1) bi = NB - 1;
#define TRI_START(r) ((r) * NB - ((r) * ((r) - 1)) / 2)
    while (bi + 1 < NB && TRI_START(bi + 1) <= t) ++bi;
    while (bi > 0 && TRI_START(bi) > t) --bi;
    int bj = bi + (t - TRI_START(bi));
#undef TRI_START

    const char* pa = (const char*)(g_pa + (size_t)bi * 128 * KPACK);
    const char* pb = (const char*)(g_pa + (size_t)bj * 128 * KPACK);
    const int ROWB = KPACK * 2;

    int seg = tid & 7, r0 = tid >> 3;

#define LOAD_CHUNK(c, buf) do { \
    int cb_ = ((c) < 4) ? (c) : (((c) < 8) ? (c) + 4 : (c) - 4); \
    uint32_t abase_ = sbase + (buf) * BUF_BYTES; \
    uint32_t bbase_ = abase_ + 16384; \
    _Pragma("unroll") \
    for (int it = 0; it < 4; ++it) { \
        int row = r0 + it * 32; \
        uint32_t off = row * 128 + seg * 16; \
        off = off ^ ((off >> 3) & 0x70); \
        CP_ASYNC16(abase_ + off, pa + (size_t)row * ROWB + (c) * 128 + seg * 16); \
        CP_ASYNC16(bbase_ + off, pb + (size_t)row * ROWB + cb_ * 128 + seg * 16); \
    } \
    CP_COMMIT(); \
} while (0)

    int wr = wid >> 2, wc = wid & 3;
    int wm = wr * 64, wn = wc * 32;

    float acc[4][4][4];
#pragma unroll
    for (int mt = 0; mt < 4; ++mt)
#pragma unroll
        for (int nt = 0; nt < 4; ++nt)
#pragma unroll
            for (int e = 0; e < 4; ++e) acc[mt][nt][e] = 0.f;

    LOAD_CHUNK(0, 0);
    LOAD_CHUNK(1, 1);
    for (int c = 0; c < NCHUNK; ++c) {
        if (c == NCHUNK - 1) CP_WAIT(0);
        else                 CP_WAIT(1);
        __syncthreads();
        if (c + 2 < NCHUNK) LOAD_CHUNK(c + 2, (c + 2) % 3);

        uint32_t abase = sbase + (c % 3) * BUF_BYTES;
        uint32_t bbase = abase + 16384;
#pragma unroll
        for (int kk = 0; kk < 4; ++kk) {
            uint32_t afr[4][4], bfr[4][2];
#pragma unroll
            for (int mt = 0; mt < 4; ++mt) {
                int row = wm + mt * 16 + (lane & 15);
                uint32_t off = row * 128 + kk * 32 + (lane >> 4) * 16;
                off = off ^ ((off >> 3) & 0x70);
                LDMATRIX_X4(afr[mt], abase + off);
            }
#pragma unroll
            for (int np = 0; np < 2; ++np) {
                int row = wn + np * 16 + ((lane >> 4) << 3) + (lane & 7);
                uint32_t off = row * 128 + kk * 32 + (((lane >> 3) & 1) << 4);
                off = off ^ ((off >> 3) & 0x70);
                uint32_t q[4];
                LDMATRIX_X4(q, bbase + off);
                bfr[np * 2 + 0][0] = q[0]; bfr[np * 2 + 0][1] = q[1];
                bfr[np * 2 + 1][0] = q[2]; bfr[np * 2 + 1][1] = q[3];
            }
#pragma unroll
            for (int mt = 0; mt < 4; ++mt)
#pragma unroll
                for (int nt = 0; nt < 4; ++nt)
                    MMA_BF16(acc[mt][nt], afr[mt], bfr[nt]);
        }
    }

    __shared__ float ssq[256];
    float* s_tile = (float*)(smem_raw + (sbase - sraw));
    if (tid < 128) ssq[tid] = g_sq[bi * 128 + tid];
    else           ssq[tid] = g_sq[bj * 128 + (tid - 128)];
    __syncthreads();

    int g4 = lane >> 2, t4 = lane & 3;
#pragma unroll
    for (int mt = 0; mt < 4; ++mt) {
#pragma unroll
        for (int half = 0; half < 2; ++half) {
            int r = wm + mt * 16 + g4 + half * 8;
            int gi = bi * 128 + r;
            float sqi = ssq[r];
#pragma unroll
            for (int nt = 0; nt < 4; ++nt) {
                int col = wn + nt * 8 + 2 * t4;
                int gj = bj * 128 + col;
                float2 o;
                float d0 = sqi + ssq[128 + col] + EPS_F
                           - 2.0f * acc[mt][nt][half * 2 + 0];
                float d1 = sqi + ssq[128 + col + 1] + EPS_F
                           - 2.0f * acc[mt][nt][half * 2 + 1];
                o.x = sqrtf(fmaxf(d0, 1e-12f));
                o.y = sqrtf(fmaxf(d1, 1e-12f));
                if (gi == gj)     o.x = sqrtf(EPS_F);
                if (gi == gj + 1) o.y = sqrtf(EPS_F);
                *(float2*)(g_dist + (size_t)gi * n + gj) = o;
                s_tile[r * TLDA + col]     = o.x;
                s_tile[r * TLDA + col + 1] = o.y;
            }
        }
    }

    if (bi != bj) {
        __syncthreads();
#pragma unroll
        for (int it = 0; it < 16; ++it) {
            int c = it * 8 + wid;
            float* orow = g_dist + (size_t)(bj * 128 + c) * n + bi * 128;
#pragma unroll
            for (int q = 0; q < 4; ++q) {
                int r = lane + q * 32;
                orow[r] = s_tile[r * TLDA + c];
            }
        }
    }
#undef LOAD_CHUNK
}

// ===========================================================================
// Row kernel: thresholded selection (exact fallback) + branchless expf.
// Intra: self excluded (d(i,i)=sqrt(eps) is always combined rank 0), so only
// top-4 of real intra needed (combined[4] = real[3]). Inter: top-7.
// ===========================================================================
template <int N>
__device__ __forceinline__ void insertN(float (&t)[N], float x) {
    if (x < t[N - 1]) {
        t[N - 1] = x;
#pragma unroll
        for (int k = N - 1; k > 0; --k) {
            float a = t[k - 1], b = t[k];
            t[k - 1] = fminf(a, b); t[k] = fmaxf(a, b);
        }
    }
}

template <int N>
__device__ __forceinline__ void warp_popN(float (&t)[N], int lane, float* out) {
#pragma unroll
    for (int r = 0; r < N; ++r) {
        float bv = t[0]; int bl = lane;
#pragma unroll
        for (int off = 16; off; off >>= 1) {
            float ov = __shfl_down_sync(0xffffffffu, bv, off);
            int   ol = __shfl_down_sync(0xffffffffu, bl, off);
            if (ov < bv) { bv = ov; bl = ol; }
        }
        bv = __shfl_sync(0xffffffffu, bv, 0);
        bl = __shfl_sync(0xffffffffu, bl, 0);
        if (lane == bl) {
#pragma unroll
            for (int k = 0; k < N - 1; ++k) t[k] = t[k + 1];
            t[N - 1] = INF_F;
        }
        if (lane == 0) out[r] = bv;
    }
}

__global__ void __launch_bounds__(256) row_kernel(int n, float* __restrict__ out) {
    __shared__ float s_mw[2][8];
    __shared__ int   s_cw[2][8];
    __shared__ float s_pop[2][8][8];
    __shared__ float s_res[2][2];
    __shared__ float s_sum[2][8];
    __shared__ float s_red[256];
    __shared__ int   s_last;

    int i = blockIdx.x, tid = threadIdx.x;
    int wid = tid >> 5, lane = tid & 31;
    const float* drow = g_dist + (size_t)i * n;
    int mycam = g_cam[i];

    float v[16];
    unsigned mk = 0;
#pragma unroll
    for (int w = 0; w < 4; ++w) {
        int j = tid * 4 + w * 1024;
        float4 f = *(const float4*)(drow + j);
        v[w*4+0]=f.x; v[w*4+1]=f.y; v[w*4+2]=f.z; v[w*4+3]=f.w;
        uchar4 cc = ((const uchar4*)g_cam)[j >> 2];
        if (cc.x == mycam) mk |= 1u << (w*4+0);
        if (cc.y == mycam) mk |= 1u << (w*4+1);
        if (cc.z == mycam) mk |= 1u << (w*4+2);
        if (cc.w == mycam) mk |= 1u << (w*4+3);
        // self -> INF (excluded from everything; accounted analytically)
        if (j     == i) v[w*4+0] = INF_F;
        if (j + 1 == i) v[w*4+1] = INF_F;
        if (j + 2 == i) v[w*4+2] = INF_F;
        if (j + 3 == i) v[w*4+3] = INF_F;
    }

    // ---- pass A: block mins (self already INF)
    float mnI = INF_F, mnE = INF_F;
#pragma unroll
    for (int k = 0; k < 16; ++k) {
        if ((mk >> k) & 1) mnI = fminf(mnI, v[k]);
        else               mnE = fminf(mnE, v[k]);
    }
#pragma unroll
    for (int off = 16; off; off >>= 1) {
        mnI = fminf(mnI, __shfl_xor_sync(0xffffffffu, mnI, off));
        mnE = fminf(mnE, __shfl_xor_sync(0xffffffffu, mnE, off));
    }
    if (lane == 0) { s_mw[0][wid] = mnI; s_mw[1][wid] = mnE; }
    __syncthreads();
    float mI = INF_F, mE = INF_F;
#pragma unroll
    for (int w = 0; w < 8; ++w) { mI = fminf(mI, s_mw[0][w]); mE = fminf(mE, s_mw[1][w]); }
    float thrI = mI + DELTA, thrE = mE + DELTA;

    // ---- pass B: thresholded inserts
    float t4I[4], t7E[7];
#pragma unroll
    for (int k = 0; k < 4; ++k) t4I[k] = INF_F;
#pragma unroll
    for (int k = 0; k < 7; ++k) t7E[k] = INF_F;
    int cI = 0, cE = 0, pI = 0;
#pragma unroll
    for (int k = 0; k < 16; ++k) {
        float x = v[k];
        if ((mk >> k) & 1) {
            pI++;
            if (x < thrI) { insertN<4>(t4I, x); cI++; }
        } else {
            if (x < thrE) { insertN<7>(t7E, x); cE++; }
        }
    }
    int pk1 = cI | (cE << 16), pk2 = pI;
#pragma unroll
    for (int off = 16; off; off >>= 1) {
        pk1 += __shfl_xor_sync(0xffffffffu, pk1, off);
        pk2 += __shfl_xor_sync(0xffffffffu, pk2, off);
    }
    if (lane == 0) { s_cw[0][wid] = pk1; s_cw[1][wid] = pk2; }
    __syncthreads();
    int C1 = 0, C2 = 0;
#pragma unroll
    for (int w = 0; w < 8; ++w) { C1 += s_cw[0][w]; C2 += s_cw[1][w]; }
    int CI = C1 & 0xffff, CE = C1 >> 16;
    int TIr = C2 - 1;          // real intra count (self excluded)
    int TE  = n - C2;

    bool validI = (CI >= 4) || (CI == TIr);
    bool validE = (CE >= 7) || (CE == TE);
    if (!(validI && validE)) {
        // exact fallback: full inserts (rare; distribution-independent safety)
#pragma unroll
        for (int k = 0; k < 4; ++k) t4I[k] = INF_F;
#pragma unroll
        for (int k = 0; k < 7; ++k) t7E[k] = INF_F;
#pragma unroll
        for (int k = 0; k < 16; ++k) {
            if ((mk >> k) & 1) insertN<4>(t4I, v[k]);
            else               insertN<7>(t7E, v[k]);
        }
    }

    warp_popN<4>(t4I, lane, &s_pop[0][wid][0]);
    if (lane == 0) { s_pop[0][wid][4] = INF_F; s_pop[0][wid][5] = INF_F; s_pop[0][wid][6] = INF_F; }
    warp_popN<7>(t7E, lane, &s_pop[1][wid][0]);
    __syncthreads();

    // ---- merge 8 sorted lists; wid0: intra Kidx=3, wid1: inter Kidx=6
    if (wid < 2) {
        float u[7];
#pragma unroll
        for (int k = 0; k < 7; ++k) u[k] = (lane < 8) ? s_pop[wid][lane][k] : INF_F;
        int Kidx = (wid == 0) ? 3 : 6;
        float d0 = INF_F, dK = INF_F;
#pragma unroll
        for (int r = 0; r < 7; ++r) {
            float bv = u[0]; int bl = lane;
#pragma unroll
            for (int off = 16; off; off >>= 1) {
                float ov = __shfl_down_sync(0xffffffffu, bv, off);
                int   ol = __shfl_down_sync(0xffffffffu, bl, off);
                if (ov < bv) { bv = ov; bl = ol; }
            }
            bv = __shfl_sync(0xffffffffu, bv, 0);
            bl = __shfl_sync(0xffffffffu, bl, 0);
            if (lane == bl) {
#pragma unroll
                for (int k = 0; k < 6; ++k) u[k] = u[k + 1];
                u[6] = INF_F;
            }
            if (r == 0) d0 = bv;
            if (r == Kidx) dK = bv;
        }
        if (lane == 0) { s_res[wid][0] = d0; s_res[wid][1] = dK; }
    }
    __syncthreads();

    // ---- pass C: branchless expf sum over rank >= K (v == INF contributes 0)
    float dKi = s_res[0][1], dKe = s_res[1][1];
    float si = 0.f, se = 0.f;
#pragma unroll
    for (int k = 0; k < 16; ++k) {
        float x = v[k];
        bool m = (mk >> k) & 1;
        float dk = m ? dKi : dKe;
        float e = __expf(SCALE_F * (dk - x));   // x=INF -> 0; dk=INF guarded below
        e = (x >= dk) ? e : 0.f;
        if (m) si += e; else se += e;
    }
#pragma unroll
    for (int off = 16; off; off >>= 1) {
        si += __shfl_xor_sync(0xffffffffu, si, off);
        se += __shfl_xor_sync(0xffffffffu, se, off);
    }
    if (lane == 0) { s_sum[0][wid] = si; s_sum[1][wid] = se; }
    __syncthreads();

    if (tid == 0) {
        float Si = 0.f, Se = 0.f;
#pragma unroll
        for (int w = 0; w < 8; ++w) { Si += s_sum[0][w]; Se += s_sum[1][w]; }
        float d0i = sqrtf(EPS_F);               // self is always intra rank 0
        float d0e = s_res[1][0];
        float term_i = 0.f, term_e = 0.f;
        if (isfinite(dKi))
            term_i = fmaxf(SCALE_F * (d0i - dKi) + logf(Si) + 40.0f, 0.f);
        if (isfinite(dKe))
            term_e = fmaxf(SCALE_F * (d0e - dKe) + logf(Se) + 6.0f, 0.f);
        g_partial[i] = term_i + 0.5f * term_e;
        __threadfence();
        int old = atomicAdd(&g_ctr, 1);
        s_last = (old == n - 1);
    }
    __syncthreads();

    if (s_last) {
        float s = 0.f;
        for (int j = tid; j < n; j += 256) s += g_partial[j];
        s_red[tid] = s;
        __syncthreads();
        for (int st = 128; st; st >>= 1) {
            if (tid < st) s_red[tid] += s_red[tid + st];
            __syncthreads();
        }
        if (tid == 0) { out[0] = s_red[0] / (float)n; g_ctr = 0; }
    }
}

// ===========================================================================
extern "C" void kernel_launch(void* const* d_in, const int* in_sizes, int n_in,
                              void* d_out, int out_size) {
    const float* feat = (const float*)d_in[0];
    const int*   cam  = (const int*)d_in[1];
    int n = in_sizes[1];
    int d = in_sizes[0] / n;
    int NB = n / 128;

    static int smem_set = 0;
    if (!smem_set) {
        cudaFuncSetAttribute(dist_gemm_mma,
                             cudaFuncAttributeMaxDynamicSharedMemorySize,
                             SMEM_GEMM_TOTAL);
        smem_set = 1;
    }

    int rowBlocks = (n + 7) / 8;
    prep_fused_kernel<<<rowBlocks + 1, 256>>>(feat, cam, n, d, rowBlocks);
    dist_gemm_mma<<<NB * (NB + 1) / 2, 256, SMEM_GEMM_TOTAL>>>(n);
    row_kernel<<<n, 256>>>(n, (float*)d_out);
}

// round 10
// speedup vs baseline: 1.3308x; 1.0819x over previous
#include <cuda_runtime.h>
#include <cuda_bf16.h>
#include <math.h>
#include <stdint.h>

#define NMAX 4096
#define DMAX 256
#define KPACK 768              // A pack: [hi|hi|lo]; B = chunk-permutation of A
#define SCALE_F 10.0f
#define EPS_F 1e-5f
#define INF_F __int_as_float(0x7f800000)

__device__ float g_dist[(size_t)NMAX * NMAX];
__device__ float g_sq[NMAX];
__device__ unsigned char g_cam[NMAX];
__device__ float g_partial[NMAX];
__device__ int g_ctr = 0;
__device__ __nv_bfloat16 g_pa[(size_t)NMAX * KPACK];

__device__ __forceinline__ uint32_t smem_to_u32(const void* p) {
    uint32_t a;
    asm("{ .reg .u64 t; cvta.to.shared.u64 t, %1; cvt.u32.u64 %0, t; }"
        : "=r"(a) : "l"(p));
    return a;
}

#define LDMATRIX_X4(R, addr) \
    asm volatile("ldmatrix.sync.aligned.m8n8.x4.shared.b16 {%0,%1,%2,%3}, [%4];" \
        : "=r"((R)[0]), "=r"((R)[1]), "=r"((R)[2]), "=r"((R)[3]) : "r"(addr))
#define MMA_BF16(D, A, B) \
    asm volatile("mma.sync.aligned.m16n8k16.row.col.f32.bf16.bf16.f32 " \
        "{%0,%1,%2,%3}, {%4,%5,%6,%7}, {%8,%9}, {%0,%1,%2,%3};" \
        : "+f"((D)[0]), "+f"((D)[1]), "+f"((D)[2]), "+f"((D)[3]) \
        : "r"((A)[0]), "r"((A)[1]), "r"((A)[2]), "r"((A)[3]), \
          "r"((B)[0]), "r"((B)[1]))
#define CP_ASYNC16(dst, src) \
    asm volatile("cp.async.cg.shared.global [%0], [%1], 16;" \
        :: "r"(dst), "l"(src))
#define CP_COMMIT() asm volatile("cp.async.commit_group;")
#define CP_WAIT(N)  asm volatile("cp.async.wait_group %0;" :: "n"(N))

// ===========================================================================
// Fused prep: warp-per-row split+pack+sq  |  camid normalize + counter reset
// ===========================================================================
__global__ void prep_fused_kernel(const float* __restrict__ f,
                                  const int* __restrict__ cam_raw,
                                  int n, int d, int rowBlocks) {
    int b = blockIdx.x;
    if (b < rowBlocks) {
        int row  = b * 8 + (threadIdx.x >> 5);
        int lane = threadIdx.x & 31;
        if (row >= n) return;
        const float4* src = (const float4*)(f + (size_t)row * d) + lane * 2;
        float4 x0 = src[0], x1 = src[1];
        float xv[8] = {x0.x, x0.y, x0.z, x0.w, x1.x, x1.y, x1.z, x1.w};
        float s = 0.f;
        uint32_t hu[4], lu[4];
#pragma unroll
        for (int q = 0; q < 4; ++q) {
            float a = xv[2 * q], c = xv[2 * q + 1];
            s += a * a + c * c;
            __nv_bfloat16 h0 = __float2bfloat16_rn(a);
            __nv_bfloat16 h1 = __float2bfloat16_rn(c);
            __nv_bfloat16 l0 = __float2bfloat16_rn(a - __bfloat162float(h0));
            __nv_bfloat16 l1 = __float2bfloat16_rn(c - __bfloat162float(h1));
            __nv_bfloat162 hh(h0, h1), ll(l0, l1);
            hu[q] = *(uint32_t*)&hh;
            lu[q] = *(uint32_t*)&ll;
        }
#pragma unroll
        for (int off = 16; off; off >>= 1) s += __shfl_down_sync(0xffffffffu, s, off);
        if (lane == 0) g_sq[row] = s;

        uint4 hv = make_uint4(hu[0], hu[1], hu[2], hu[3]);
        uint4 lv = make_uint4(lu[0], lu[1], lu[2], lu[3]);
        uint4* pa4 = (uint4*)(g_pa + (size_t)row * KPACK);
        pa4[lane] = hv; pa4[32 + lane] = hv; pa4[64 + lane] = lv;
    } else {
        __shared__ int s_is64;
        if (threadIdx.x == 0) {
            g_ctr = 0;
            int is64 = 1;
            int checks = n < 128 ? n : 128;
            for (int k = 0; k < checks; ++k)
                if (cam_raw[2 * k + 1] != 0) { is64 = 0; break; }
            s_is64 = is64;
        }
        __syncthreads();
        int is64 = s_is64;
        for (int j = threadIdx.x; j < n; j += blockDim.x)
            g_cam[j] = (unsigned char)(is64 ? cam_raw[2 * j] : cam_raw[j]);
    }
}

// ===========================================================================
// Distance GEMM via mma.sync bf16, UPPER-TRIANGLE blocks only. (unchanged)
// ===========================================================================
#define NCHUNK (KPACK / 64)
#define BUF_BYTES 32768
#define TLDA 129
#define SMEM_GEMM_TOTAL (1024 + 3 * BUF_BYTES)

__global__ void __launch_bounds__(256, 2) dist_gemm_mma(int n) {
    extern __shared__ char smem_raw[];
    uint32_t sraw = smem_to_u32(smem_raw);
    uint32_t sbase = (sraw + 1023) & ~1023u;
    int tid = threadIdx.x, lane = tid & 31, wid = tid >> 5;

    int NB = n >> 7;
    int t = blockIdx.x;
    int bi = (int)((2.0f * NB + 1.0f -
                    sqrtf((2.0f * NB + 1.0f) * (2.0f * NB + 1.0f) - 8.0f * t)) * 0.5f);
    if (bi < 0) bi = 0;
    if (bi > NB - 1) bi = NB - 1;
#define TRI_START(r) ((r) * NB - ((r) * ((r) - 1)) / 2)
    while (bi + 1 < NB && TRI_START(bi + 1) <= t) ++bi;
    while (bi > 0 && TRI_START(bi) > t) --bi;
    int bj = bi + (t - TRI_START(bi));
#undef TRI_START

    const char* pa = (const char*)(g_pa + (size_t)bi * 128 * KPACK);
    const char* pb = (const char*)(g_pa + (size_t)bj * 128 * KPACK);
    const int ROWB = KPACK * 2;

    int seg = tid & 7, r0 = tid >> 3;

#define LOAD_CHUNK(c, buf) do { \
    int cb_ = ((c) < 4) ? (c) : (((c) < 8) ? (c) + 4 : (c) - 4); \
    uint32_t abase_ = sbase + (buf) * BUF_BYTES; \
    uint32_t bbase_ = abase_ + 16384; \
    _Pragma("unroll") \
    for (int it = 0; it < 4; ++it) { \
        int row = r0 + it * 32; \
        uint32_t off = row * 128 + seg * 16; \
        off = off ^ ((off >> 3) & 0x70); \
        CP_ASYNC16(abase_ + off, pa + (size_t)row * ROWB + (c) * 128 + seg * 16); \
        CP_ASYNC16(bbase_ + off, pb + (size_t)row * ROWB + cb_ * 128 + seg * 16); \
    } \
    CP_COMMIT(); \
} while (0)

    int wr = wid >> 2, wc = wid & 3;
    int wm = wr * 64, wn = wc * 32;

    float acc[4][4][4];
#pragma unroll
    for (int mt = 0; mt < 4; ++mt)
#pragma unroll
        for (int nt = 0; nt < 4; ++nt)
#pragma unroll
            for (int e = 0; e < 4; ++e) acc[mt][nt][e] = 0.f;

    LOAD_CHUNK(0, 0);
    LOAD_CHUNK(1, 1);
    for (int c = 0; c < NCHUNK; ++c) {
        if (c == NCHUNK - 1) CP_WAIT(0);
        else                 CP_WAIT(1);
        __syncthreads();
        if (c + 2 < NCHUNK) LOAD_CHUNK(c + 2, (c + 2) % 3);

        uint32_t abase = sbase + (c % 3) * BUF_BYTES;
        uint32_t bbase = abase + 16384;
#pragma unroll
        for (int kk = 0; kk < 4; ++kk) {
            uint32_t afr[4][4], bfr[4][2];
#pragma unroll
            for (int mt = 0; mt < 4; ++mt) {
                int row = wm + mt * 16 + (lane & 15);
                uint32_t off = row * 128 + kk * 32 + (lane >> 4) * 16;
                off = off ^ ((off >> 3) & 0x70);
                LDMATRIX_X4(afr[mt], abase + off);
            }
#pragma unroll
            for (int np = 0; np < 2; ++np) {
                int row = wn + np * 16 + ((lane >> 4) << 3) + (lane & 7);
                uint32_t off = row * 128 + kk * 32 + (((lane >> 3) & 1) << 4);
                off = off ^ ((off >> 3) & 0x70);
                uint32_t q[4];
                LDMATRIX_X4(q, bbase + off);
                bfr[np * 2 + 0][0] = q[0]; bfr[np * 2 + 0][1] = q[1];
                bfr[np * 2 + 1][0] = q[2]; bfr[np * 2 + 1][1] = q[3];
            }
#pragma unroll
            for (int mt = 0; mt < 4; ++mt)
#pragma unroll
                for (int nt = 0; nt < 4; ++nt)
                    MMA_BF16(acc[mt][nt], afr[mt], bfr[nt]);
        }
    }

    __shared__ float ssq[256];
    float* s_tile = (float*)(smem_raw + (sbase - sraw));
    if (tid < 128) ssq[tid] = g_sq[bi * 128 + tid];
    else           ssq[tid] = g_sq[bj * 128 + (tid - 128)];
    __syncthreads();

    int g4 = lane >> 2, t4 = lane & 3;
#pragma unroll
    for (int mt = 0; mt < 4; ++mt) {
#pragma unroll
        for (int half = 0; half < 2; ++half) {
            int r = wm + mt * 16 + g4 + half * 8;
            int gi = bi * 128 + r;
            float sqi = ssq[r];
#pragma unroll
            for (int nt = 0; nt < 4; ++nt) {
                int col = wn + nt * 8 + 2 * t4;
                int gj = bj * 128 + col;
                float2 o;
                float d0 = sqi + ssq[128 + col] + EPS_F
                           - 2.0f * acc[mt][nt][half * 2 + 0];
                float d1 = sqi + ssq[128 + col + 1] + EPS_F
                           - 2.0f * acc[mt][nt][half * 2 + 1];
                o.x = sqrtf(fmaxf(d0, 1e-12f));
                o.y = sqrtf(fmaxf(d1, 1e-12f));
                if (gi == gj)     o.x = sqrtf(EPS_F);
                if (gi == gj + 1) o.y = sqrtf(EPS_F);
                *(float2*)(g_dist + (size_t)gi * n + gj) = o;
                s_tile[r * TLDA + col]     = o.x;
                s_tile[r * TLDA + col + 1] = o.y;
            }
        }
    }

    if (bi != bj) {
        __syncthreads();
#pragma unroll
        for (int it = 0; it < 16; ++it) {
            int c = it * 8 + wid;
            float* orow = g_dist + (size_t)(bj * 128 + c) * n + bi * 128;
#pragma unroll
            for (int q = 0; q < 4; ++q) {
                int r = lane + q * 32;
                orow[r] = s_tile[r * TLDA + c];
            }
        }
    }
#undef LOAD_CHUNK
}

// ===========================================================================
// Row kernel v3: ONE WARP PER ROW, no block-wide phases in the hot path.
// Pass 1: per-lane guarded inserts (top-4 intra real / top-7 inter) over 128
//         elems/lane. Pass M: 11-round pure-shfl merge. Pass 2: streamed
//         branchless expf sums (L2-hot). Self handled analytically.
// ===========================================================================
template <int N>
__device__ __forceinline__ void insertN(float (&t)[N], float x) {
    if (x < t[N - 1]) {
        t[N - 1] = x;
#pragma unroll
        for (int k = N - 1; k > 0; --k) {
            float a = t[k - 1], b = t[k];
            t[k - 1] = fminf(a, b); t[k] = fmaxf(a, b);
        }
    }
}

// merge per-lane sorted lists across the warp; out[r] broadcast to all lanes
template <int N>
__device__ __forceinline__ void warp_merge(float (&t)[N], int lane, float (&out)[N]) {
#pragma unroll
    for (int r = 0; r < N; ++r) {
        float bv = t[0]; int bl = lane;
#pragma unroll
        for (int off = 16; off; off >>= 1) {
            float ov = __shfl_down_sync(0xffffffffu, bv, off);
            int   ol = __shfl_down_sync(0xffffffffu, bl, off);
            if (ov < bv) { bv = ov; bl = ol; }
        }
        bv = __shfl_sync(0xffffffffu, bv, 0);
        bl = __shfl_sync(0xffffffffu, bl, 0);
        if (lane == bl) {
#pragma unroll
            for (int k = 0; k < N - 1; ++k) t[k] = t[k + 1];
            t[N - 1] = INF_F;
        }
        out[r] = bv;
    }
}

__global__ void __launch_bounds__(256) row_kernel(int n, int nCtas,
                                                  float* __restrict__ out) {
    __shared__ unsigned char s_cam[NMAX];
    __shared__ float s_part[8];
    __shared__ float s_red[256];
    __shared__ int   s_last;

    int tid = threadIdx.x, wid = tid >> 5, lane = tid & 31;
    int row = blockIdx.x * 8 + wid;

    // stage camids once per CTA
    for (int j = tid; j < n / 16; j += 256)
        ((uint4*)s_cam)[j] = ((const uint4*)g_cam)[j];
    __syncthreads();

    int mycam = s_cam[row];
    const float4* drow4 = (const float4*)(g_dist + (size_t)row * n);
    int nIter = n >> 7;                   // 128 elems per warp-iteration

    // ---- pass 1: guarded inserts
    float t4I[4], t7E[7];
#pragma unroll
    for (int k = 0; k < 4; ++k) t4I[k] = INF_F;
#pragma unroll
    for (int k = 0; k < 7; ++k) t7E[k] = INF_F;

#pragma unroll 4
    for (int it = 0; it < nIter; ++it) {
        int j4 = it * 32 + lane;
        float4 f = drow4[j4];
        uchar4 cc = ((const uchar4*)s_cam)[j4];
        int jb = j4 << 2;
        float x0 = (jb     == row) ? INF_F : f.x;
        float x1 = (jb + 1 == row) ? INF_F : f.y;
        float x2 = (jb + 2 == row) ? INF_F : f.z;
        float x3 = (jb + 3 == row) ? INF_F : f.w;
        if (cc.x == mycam) insertN<4>(t4I, x0); else insertN<7>(t7E, x0);
        if (cc.y == mycam) insertN<4>(t4I, x1); else insertN<7>(t7E, x1);
        if (cc.z == mycam) insertN<4>(t4I, x2); else insertN<7>(t7E, x2);
        if (cc.w == mycam) insertN<4>(t4I, x3); else insertN<7>(t7E, x3);
    }

    // ---- merge across warp (no smem)
    float mI[4], mEv[7];
    warp_merge<4>(t4I, lane, mI);
    warp_merge<7>(t7E, lane, mEv);
    float dKi = mI[3];                   // combined intra rank 4 (self = rank 0)
    float d0e = mEv[0], dKe = mEv[6];

    // ---- pass 2: branchless expf sums (L2-hot reload)
    float si = 0.f, se = 0.f;
#pragma unroll 4
    for (int it = 0; it < nIter; ++it) {
        int j4 = it * 32 + lane;
        float4 f = drow4[j4];
        uchar4 cc = ((const uchar4*)s_cam)[j4];
        int jb = j4 << 2;
        float x0 = (jb     == row) ? INF_F : f.x;
        float x1 = (jb + 1 == row) ? INF_F : f.y;
        float x2 = (jb + 2 == row) ? INF_F : f.z;
        float x3 = (jb + 3 == row) ? INF_F : f.w;
#define ACC1(cm, xx) do { \
        bool m_ = (cm == mycam); \
        float dk_ = m_ ? dKi : dKe; \
        float e_ = __expf(SCALE_F * (dk_ - (xx))); \
        e_ = ((xx) >= dk_) ? e_ : 0.f; \
        if (m_) si += e_; else se += e_; } while (0)
        ACC1(cc.x, x0); ACC1(cc.y, x1); ACC1(cc.z, x2); ACC1(cc.w, x3);
#undef ACC1
    }
#pragma unroll
    for (int off = 16; off; off >>= 1) {
        si += __shfl_xor_sync(0xffffffffu, si, off);
        se += __shfl_xor_sync(0xffffffffu, se, off);
    }

    if (lane == 0) {
        float d0i = sqrtf(EPS_F);        // self is always intra rank 0
        float term_i = 0.f, term_e = 0.f;
        if (isfinite(dKi))
            term_i = fmaxf(SCALE_F * (d0i - dKi) + logf(si) + 40.0f, 0.f);
        if (isfinite(dKe))
            term_e = fmaxf(SCALE_F * (d0e - dKe) + logf(se) + 6.0f, 0.f);
        s_part[wid] = term_i + 0.5f * term_e;
    }
    __syncthreads();

    if (tid == 0) {
        float p = 0.f;
#pragma unroll
        for (int w = 0; w < 8; ++w) p += s_part[w];
        g_partial[blockIdx.x] = p;
        __threadfence();
        int old = atomicAdd(&g_ctr, 1);
        s_last = (old == nCtas - 1);
    }
    __syncthreads();

    if (s_last) {
        float s = 0.f;
        for (int j = tid; j < nCtas; j += 256) s += g_partial[j];
        s_red[tid] = s;
        __syncthreads();
        for (int st = 128; st; st >>= 1) {
            if (tid < st) s_red[tid] += s_red[tid + st];
            __syncthreads();
        }
        if (tid == 0) { out[0] = s_red[0] / (float)n; g_ctr = 0; }
    }
}

// ===========================================================================
extern "C" void kernel_launch(void* const* d_in, const int* in_sizes, int n_in,
                              void* d_out, int out_size) {
    const float* feat = (const float*)d_in[0];
    const int*   cam  = (const int*)d_in[1];
    int n = in_sizes[1];
    int d = in_sizes[0] / n;
    int NB = n / 128;

    static int smem_set = 0;
    if (!smem_set) {
        cudaFuncSetAttribute(dist_gemm_mma,
                             cudaFuncAttributeMaxDynamicSharedMemorySize,
                             SMEM_GEMM_TOTAL);
        smem_set = 1;
    }

    int rowBlocks = (n + 7) / 8;
    prep_fused_kernel<<<rowBlocks + 1, 256>>>(feat, cam, n, d, rowBlocks);
    dist_gemm_mma<<<NB * (NB + 1) / 2, 256, SMEM_GEMM_TOTAL>>>(n);
    int nCtas = n / 8;
    row_kernel<<<nCtas, 256>>>(n, nCtas, (float*)d_out);
}